// round 5
// baseline (speedup 1.0000x reference)
#include <cuda_runtime.h>
#include <cstdint>

// Problem constants
constexpr int Hd = 1024;   // hidden
constexpr int Ff = 4096;   // intermediate
constexpr int NE = 8;      // experts
constexpr int NT = 2048;   // tokens (2 * 1024)
constexpr int NA = 2 * NT; // assignments (top-2)

constexpr int BM = 64, BN = 64, BK = 16;

// ---------------- device scratch (no allocations allowed) ----------------
__device__ int   g_cnt[NE];
__device__ int   g_tok[NE][NT];    // bucket -> token
__device__ float g_wt[NE][NT];     // bucket -> combine weight
__device__ int   g_slot[NE][NT];   // bucket -> rank slot (0/1)
__device__ float g_h[(size_t)NA * Ff];   // 64 MB fp32 intermediate, row = tok*2+slot
__device__ float g_sbuf[2 * NT * Hd];    // per-rank-slot output buffers (16 MB)

// ---------------- helpers ----------------
__device__ __forceinline__ float f2tf(float x) {
    unsigned u;
    asm("cvt.rna.tf32.f32 %0, %1;" : "=r"(u) : "f"(x));
    return __uint_as_float(u);
}
__device__ __forceinline__ float4 tf4(float4 v) {
    return make_float4(f2tf(v.x), f2tf(v.y), f2tf(v.z), f2tf(v.w));
}

__device__ __forceinline__ void mma8(float c[4], const unsigned a[4], const unsigned b[2]) {
    asm volatile(
        "mma.sync.aligned.m16n8k8.row.col.f32.tf32.tf32.f32 "
        "{%0,%1,%2,%3},{%4,%5,%6,%7},{%8,%9},{%0,%1,%2,%3};"
        : "+f"(c[0]), "+f"(c[1]), "+f"(c[2]), "+f"(c[3])
        : "r"(a[0]), "r"(a[1]), "r"(a[2]), "r"(a[3]), "r"(b[0]), "r"(b[1]));
}

// ---------------- kernels ----------------
__global__ void zero_kernel() {
    if (threadIdx.x < NE) g_cnt[threadIdx.x] = 0;
}

// One warp per token: logits -> softmax -> top-2 -> softmax of the two PROBS.
__global__ void router_kernel(const float* __restrict__ x, const float* __restrict__ gw) {
    int tok  = blockIdx.x * 8 + (threadIdx.x >> 5);
    int lane = threadIdx.x & 31;
    if (tok >= NT) return;
    const float* xr = x + (size_t)tok * Hd;

    float acc[NE];
#pragma unroll
    for (int e = 0; e < NE; e++) acc[e] = 0.f;
    for (int i = lane; i < Hd; i += 32) {
        float xv = xr[i];
        const float* g = gw + i * NE;
#pragma unroll
        for (int e = 0; e < NE; e++) acc[e] = fmaf(xv, g[e], acc[e]);
    }
#pragma unroll
    for (int e = 0; e < NE; e++) {
#pragma unroll
        for (int o = 16; o > 0; o >>= 1) acc[e] += __shfl_xor_sync(0xffffffffu, acc[e], o);
    }
    if (lane == 0) {
        float m = acc[0];
#pragma unroll
        for (int e = 1; e < NE; e++) m = fmaxf(m, acc[e]);
        float p[NE], s = 0.f;
#pragma unroll
        for (int e = 0; e < NE; e++) { p[e] = expf(acc[e] - m); s += p[e]; }
        float inv = 1.f / s;
#pragma unroll
        for (int e = 0; e < NE; e++) p[e] *= inv;

        // top-2 (ties -> lowest index, matching jax.lax.top_k)
        int i0 = 0;
#pragma unroll
        for (int e = 1; e < NE; e++) if (p[e] > p[i0]) i0 = e;
        int i1 = (i0 == 0) ? 1 : 0;
#pragma unroll
        for (int e = 0; e < NE; e++) if (e != i0 && p[e] > p[i1]) i1 = e;

        // softmax over the two probabilities themselves
        float eb = expf(p[i1] - p[i0]);       // <= 1
        float w0 = 1.f / (1.f + eb);
        float w1 = 1.f - w0;

        int s0 = atomicAdd(&g_cnt[i0], 1);
        g_tok[i0][s0] = tok; g_wt[i0][s0] = w0; g_slot[i0][s0] = 0;
        int s1 = atomicAdd(&g_cnt[i1], 1);
        g_tok[i1][s1] = tok; g_wt[i1][s1] = w1; g_slot[i1][s1] = 1;
    }
}

// Fused gate+up GEMM per expert bucket: h[aid] = silu(X Wg) * (X Wu), X rows gathered.
__global__ void __launch_bounds__(128) gemm1_kernel(
    const float* __restrict__ x,
    const float* __restrict__ w_gate,
    const float* __restrict__ w_up)
{
    int e = blockIdx.z;
    int cnt = g_cnt[e];
    int row0 = blockIdx.y * BM;
    if (row0 >= cnt) return;
    int col0 = blockIdx.x * BN;
    const float* Bg = w_gate + (size_t)e * Hd * Ff;
    const float* Bu = w_up   + (size_t)e * Hd * Ff;

    __shared__ __align__(16) float sA[2][BM][20];
    __shared__ __align__(16) float sBg[2][BK][72];
    __shared__ __align__(16) float sBu[2][BK][72];

    int t = threadIdx.x;
    int lane = t & 31, warp = t >> 5;
    int wm = warp >> 1, wn = warp & 1;
    int qr = lane >> 2, qc = lane & 3;

    int ar[2], aseg[2];
    const float* axp[2];
#pragma unroll
    for (int i = 0; i < 2; i++) {
        int idx = t + i * 128;
        ar[i] = idx >> 2;
        aseg[i] = (idx & 3) * 4;
        int gr = row0 + ar[i];
        axp[i] = (gr < cnt) ? (x + (size_t)g_tok[e][gr] * Hd + aseg[i]) : nullptr;
    }
    int bkr[2], bnc[2];
#pragma unroll
    for (int i = 0; i < 2; i++) {
        int idx = t + i * 128;
        bkr[i] = idx >> 4;
        bnc[i] = (idx & 15) * 4;
    }

    float accG[2][4][4], accU[2][4][4];
#pragma unroll
    for (int a = 0; a < 2; a++)
#pragma unroll
        for (int b = 0; b < 4; b++)
#pragma unroll
            for (int c = 0; c < 4; c++) { accG[a][b][c] = 0.f; accU[a][b][c] = 0.f; }

    float4 la[2], lbg[2], lbu[2];

    auto fetch = [&](int kk) {
#pragma unroll
        for (int i = 0; i < 2; i++)
            la[i] = axp[i] ? *(const float4*)(axp[i] + kk) : make_float4(0, 0, 0, 0);
#pragma unroll
        for (int i = 0; i < 2; i++) {
            lbg[i] = *(const float4*)(Bg + (size_t)(kk + bkr[i]) * Ff + col0 + bnc[i]);
            lbu[i] = *(const float4*)(Bu + (size_t)(kk + bkr[i]) * Ff + col0 + bnc[i]);
        }
    };
    auto stage = [&](int buf) {
#pragma unroll
        for (int i = 0; i < 2; i++)
            *(float4*)&sA[buf][ar[i]][aseg[i]] = tf4(la[i]);
#pragma unroll
        for (int i = 0; i < 2; i++) {
            *(float4*)&sBg[buf][bkr[i]][bnc[i]] = tf4(lbg[i]);
            *(float4*)&sBu[buf][bkr[i]][bnc[i]] = tf4(lbu[i]);
        }
    };

    fetch(0); stage(0);
    __syncthreads();
    const int KT = Hd / BK;
    for (int kt = 0; kt < KT; kt++) {
        int buf = kt & 1;
        if (kt + 1 < KT) fetch((kt + 1) * BK);
#pragma unroll
        for (int ks = 0; ks < 2; ks++) {
            unsigned af[2][4];
#pragma unroll
            for (int mt = 0; mt < 2; mt++) {
                const float* ap = &sA[buf][wm * 32 + mt * 16 + qr][ks * 8 + qc];
                af[mt][0] = __float_as_uint(ap[0]);
                af[mt][1] = __float_as_uint(ap[8 * 20]);
                af[mt][2] = __float_as_uint(ap[4]);
                af[mt][3] = __float_as_uint(ap[8 * 20 + 4]);
            }
#pragma unroll
            for (int nt = 0; nt < 4; nt++) {
                int n = wn * 32 + nt * 8 + qr;
                const float* bp = &sBg[buf][ks * 8 + qc][n];
                unsigned bg[2] = { __float_as_uint(bp[0]), __float_as_uint(bp[4 * 72]) };
                const float* up = &sBu[buf][ks * 8 + qc][n];
                unsigned bu[2] = { __float_as_uint(up[0]), __float_as_uint(up[4 * 72]) };
                mma8(accG[0][nt], af[0], bg);
                mma8(accG[1][nt], af[1], bg);
                mma8(accU[0][nt], af[0], bu);
                mma8(accU[1][nt], af[1], bu);
            }
        }
        if (kt + 1 < KT) stage(buf ^ 1);
        __syncthreads();
    }

    // epilogue: h = silu(g) * u, write to assignment row tok*2+slot
#pragma unroll
    for (int mt = 0; mt < 2; mt++) {
#pragma unroll
        for (int half = 0; half < 2; half++) {
            int r = row0 + wm * 32 + mt * 16 + qr + half * 8;
            if (r < cnt) {
                int aid = g_tok[e][r] * 2 + g_slot[e][r];
                float* hrow = g_h + (size_t)aid * Ff + col0;
#pragma unroll
                for (int nt = 0; nt < 4; nt++) {
                    float gg0 = accG[mt][nt][half * 2 + 0], gg1 = accG[mt][nt][half * 2 + 1];
                    float uu0 = accU[mt][nt][half * 2 + 0], uu1 = accU[mt][nt][half * 2 + 1];
                    float h0 = gg0 * uu0 / (1.f + __expf(-gg0));
                    float h1 = gg1 * uu1 / (1.f + __expf(-gg1));
                    int c = wn * 32 + nt * 8 + 2 * qc;
                    *(float2*)(hrow + c) = make_float2(h0, h1);
                }
            }
        }
    }
}

// Down-projection per expert bucket, scaled by combine weight, written to rank-slot buffers.
__global__ void __launch_bounds__(128) gemm2_kernel(const float* __restrict__ w_down)
{
    int e = blockIdx.z;
    int cnt = g_cnt[e];
    int row0 = blockIdx.y * BM;
    if (row0 >= cnt) return;
    int col0 = blockIdx.x * BN;
    const float* Bd = w_down + (size_t)e * Ff * Hd;

    __shared__ __align__(16) float sA[2][BM][20];
    __shared__ __align__(16) float sB[2][BK][72];

    int t = threadIdx.x;
    int lane = t & 31, warp = t >> 5;
    int wm = warp >> 1, wn = warp & 1;
    int qr = lane >> 2, qc = lane & 3;

    int ar[2], aseg[2];
    const float* axp[2];
#pragma unroll
    for (int i = 0; i < 2; i++) {
        int idx = t + i * 128;
        ar[i] = idx >> 2;
        aseg[i] = (idx & 3) * 4;
        int gr = row0 + ar[i];
        if (gr < cnt) {
            int aid = g_tok[e][gr] * 2 + g_slot[e][gr];
            axp[i] = g_h + (size_t)aid * Ff + aseg[i];
        } else {
            axp[i] = nullptr;
        }
    }
    int bkr[2], bnc[2];
#pragma unroll
    for (int i = 0; i < 2; i++) {
        int idx = t + i * 128;
        bkr[i] = idx >> 4;
        bnc[i] = (idx & 15) * 4;
    }

    float acc[2][4][4];
#pragma unroll
    for (int a = 0; a < 2; a++)
#pragma unroll
        for (int b = 0; b < 4; b++)
#pragma unroll
            for (int c = 0; c < 4; c++) acc[a][b][c] = 0.f;

    float4 la[2], lb[2];
    auto fetch = [&](int kk) {
#pragma unroll
        for (int i = 0; i < 2; i++)
            la[i] = axp[i] ? *(const float4*)(axp[i] + kk) : make_float4(0, 0, 0, 0);
#pragma unroll
        for (int i = 0; i < 2; i++)
            lb[i] = *(const float4*)(Bd + (size_t)(kk + bkr[i]) * Hd + col0 + bnc[i]);
    };
    auto stage = [&](int buf) {
#pragma unroll
        for (int i = 0; i < 2; i++)
            *(float4*)&sA[buf][ar[i]][aseg[i]] = tf4(la[i]);
#pragma unroll
        for (int i = 0; i < 2; i++)
            *(float4*)&sB[buf][bkr[i]][bnc[i]] = tf4(lb[i]);
    };

    fetch(0); stage(0);
    __syncthreads();
    const int KT = Ff / BK;
    for (int kt = 0; kt < KT; kt++) {
        int buf = kt & 1;
        if (kt + 1 < KT) fetch((kt + 1) * BK);
#pragma unroll
        for (int ks = 0; ks < 2; ks++) {
            unsigned af[2][4];
#pragma unroll
            for (int mt = 0; mt < 2; mt++) {
                const float* ap = &sA[buf][wm * 32 + mt * 16 + qr][ks * 8 + qc];
                af[mt][0] = __float_as_uint(ap[0]);
                af[mt][1] = __float_as_uint(ap[8 * 20]);
                af[mt][2] = __float_as_uint(ap[4]);
                af[mt][3] = __float_as_uint(ap[8 * 20 + 4]);
            }
#pragma unroll
            for (int nt = 0; nt < 4; nt++) {
                int n = wn * 32 + nt * 8 + qr;
                const float* bp = &sB[buf][ks * 8 + qc][n];
                unsigned bb[2] = { __float_as_uint(bp[0]), __float_as_uint(bp[4 * 72]) };
                mma8(acc[0][nt], af[0], bb);
                mma8(acc[1][nt], af[1], bb);
            }
        }
        if (kt + 1 < KT) stage(buf ^ 1);
        __syncthreads();
    }

#pragma unroll
    for (int mt = 0; mt < 2; mt++) {
#pragma unroll
        for (int half = 0; half < 2; half++) {
            int r = row0 + wm * 32 + mt * 16 + qr + half * 8;
            if (r < cnt) {
                int tok = g_tok[e][r];
                float w = g_wt[e][r];
                int sl  = g_slot[e][r];
                float* orow = g_sbuf + (size_t)sl * NT * Hd + (size_t)tok * Hd + col0;
#pragma unroll
                for (int nt = 0; nt < 4; nt++) {
                    int c = wn * 32 + nt * 8 + 2 * qc;
                    *(float2*)(orow + c) = make_float2(w * acc[mt][nt][half * 2 + 0],
                                                       w * acc[mt][nt][half * 2 + 1]);
                }
            }
        }
    }
}

__global__ void combine_kernel(float* __restrict__ out) {
    int i = blockIdx.x * 256 + threadIdx.x;
    if (i < NT * Hd) out[i] = g_sbuf[i] + g_sbuf[NT * Hd + i];
}

// ---------------- launch ----------------
extern "C" void kernel_launch(void* const* d_in, const int* in_sizes, int n_in,
                              void* d_out, int out_size) {
    (void)in_sizes; (void)n_in; (void)out_size;
    const float* x      = (const float*)d_in[0];
    const float* gw     = (const float*)d_in[1];
    const float* w_gate = (const float*)d_in[2];
    const float* w_up   = (const float*)d_in[3];
    const float* w_down = (const float*)d_in[4];
    float* out = (float*)d_out;

    zero_kernel<<<1, 32>>>();
    router_kernel<<<NT / 8, 256>>>(x, gw);
    gemm1_kernel<<<dim3(Ff / BN, NT / BM, NE), 128>>>(x, w_gate, w_up);
    gemm2_kernel<<<dim3(Hd / BN, NT / BM, NE), 128>>>(w_down);
    combine_kernel<<<(NT * Hd) / 256, 256>>>(out);
}